// round 2
// baseline (speedup 1.0000x reference)
#include <cuda_runtime.h>
#include <cuda_bf16.h>
#include <cstdint>

// ---------------------------------------------------------------------------
// 2-layer bidirectional GRU. B=32, S=2048, D=256, H=256, gates=768.
//   gx = X @ W_ih^T + b_ih      (parallel GEMM)
//   per step: gh = h @ W_hh^T + b_hh
//             r=sig(xr+hr) z=sig(xz+hz) n=tanh(xn+r*hn) h'=(1-z)*n+z*h
// Both directions share weights/gx (module deepcopies the cell).
// Scan: 128 resident CTAs = 4 groups (2 dirs x 2 batch-halves of 16) x 32
// j-slices; h exchanged per step via double-buffered global buffer +
// release/acquire counter barrier.
// ---------------------------------------------------------------------------

#define S_LEN  2048
#define NBATCH 32
#define HID    256
#define G3     768
#define OUTW   512
#define NSLICE 32
#define NGROUP 4
#define BC     16
#define RPC    24          // rows of W_hh per CTA (8 j x 3 gates)
#define HPAD   260         // padded smem row stride (floats)
#define SCTH   384

// device-global scratch (no allocation allowed)
__device__ float g_gx[(size_t)NBATCH * S_LEN * G3];     // [b][s][768]
__device__ float g_out0[(size_t)NBATCH * S_LEN * OUTW]; // layer0 output
__device__ float g_hbuf[2][NGROUP][BC * HID];           // h exchange, 2 parities
__device__ unsigned int g_cnt[NGROUP];                  // barrier counters

// ---- f32x2 helpers --------------------------------------------------------
__device__ __forceinline__ void fma2(uint64_t& d, uint64_t a, uint64_t b) {
    asm("fma.rn.f32x2 %0, %1, %2, %0;" : "+l"(d) : "l"(a), "l"(b));
}
__device__ __forceinline__ uint64_t pk(float lo, float hi) {
    uint64_t r; asm("mov.b64 %0, {%1, %2};" : "=l"(r) : "f"(lo), "f"(hi)); return r;
}
__device__ __forceinline__ float upks(uint64_t v) {
    float lo, hi; asm("mov.b64 {%0, %1}, %2;" : "=f"(lo), "=f"(hi) : "l"(v));
    return lo + hi;
}

// ---------------------------------------------------------------------------
__global__ void k_init() {
    int idx = blockIdx.x * blockDim.x + threadIdx.x;
    float* p = &g_hbuf[0][0][0];
    const int total = 2 * NGROUP * BC * HID;
    for (int i = idx; i < total; i += gridDim.x * blockDim.x) p[i] = 0.f;
    if (idx < NGROUP) g_cnt[idx] = 0u;
}

// ---------------------------------------------------------------------------
// GEMM: C[m][n] = sum_k A[m][k]*W[n][k] + bias[n]
// A: [65536][K] row-major (row m = b*S + s), W: [768][K], C = g_gx [65536][768]
// Block 128(m) x 64(n), BK=8, 256 threads, per-thread 8x4, f32x2 accumulators.
// ---------------------------------------------------------------------------
__global__ void __launch_bounds__(256) k_gemm(
    const float* __restrict__ Aext, const float* __restrict__ W,
    const float* __restrict__ bias, int K, int useInternalA)
{
    __shared__ float As[8][132];
    __shared__ float Bs[8][68];

    const float* A = useInternalA ? &g_out0[0] : Aext;
    float* C = &g_gx[0];

    const int tid = threadIdx.x;
    const int bm = blockIdx.x, bn = blockIdx.y;
    const int tx = tid & 15, ty = tid >> 4;       // tx: n (4 each), ty: m (8 each)

    // loaders
    const int lr = tid >> 1, lq = (tid & 1) * 4;  // row-in-tile, k-quad
    const float* Ap = A + (size_t)(bm * 128 + lr) * K + lq;
    const float* Bp = W + (size_t)(bn * 64 + (lr & 63)) * K + lq;
    const bool loadB = (tid < 128);

    uint64_t acc[8][4];
#pragma unroll
    for (int i = 0; i < 8; ++i)
#pragma unroll
        for (int j = 0; j < 4; ++j) acc[i][j] = 0ull;

    float4 av = *(const float4*)Ap;
    float4 bv = loadB ? *(const float4*)Bp : make_float4(0.f, 0.f, 0.f, 0.f);

    for (int kt = 0; kt < K; kt += 8) {
        __syncthreads();
        As[lq + 0][lr] = av.x; As[lq + 1][lr] = av.y;
        As[lq + 2][lr] = av.z; As[lq + 3][lr] = av.w;
        if (loadB) {
            Bs[lq + 0][lr] = bv.x; Bs[lq + 1][lr] = bv.y;
            Bs[lq + 2][lr] = bv.z; Bs[lq + 3][lr] = bv.w;
        }
        __syncthreads();
        if (kt + 8 < K) {
            av = *(const float4*)(Ap + kt + 8);
            if (loadB) bv = *(const float4*)(Bp + kt + 8);
        }
#pragma unroll
        for (int k2 = 0; k2 < 4; ++k2) {
            float4 aL0 = *(const float4*)&As[2 * k2][ty * 8];
            float4 aH0 = *(const float4*)&As[2 * k2][ty * 8 + 4];
            float4 aL1 = *(const float4*)&As[2 * k2 + 1][ty * 8];
            float4 aH1 = *(const float4*)&As[2 * k2 + 1][ty * 8 + 4];
            float4 b0  = *(const float4*)&Bs[2 * k2][tx * 4];
            float4 b1  = *(const float4*)&Bs[2 * k2 + 1][tx * 4];
            uint64_t am[8], bb[4];
            am[0] = pk(aL0.x, aL1.x); am[1] = pk(aL0.y, aL1.y);
            am[2] = pk(aL0.z, aL1.z); am[3] = pk(aL0.w, aL1.w);
            am[4] = pk(aH0.x, aH1.x); am[5] = pk(aH0.y, aH1.y);
            am[6] = pk(aH0.z, aH1.z); am[7] = pk(aH0.w, aH1.w);
            bb[0] = pk(b0.x, b1.x);   bb[1] = pk(b0.y, b1.y);
            bb[2] = pk(b0.z, b1.z);   bb[3] = pk(b0.w, b1.w);
#pragma unroll
            for (int i = 0; i < 8; ++i)
#pragma unroll
                for (int j = 0; j < 4; ++j) fma2(acc[i][j], am[i], bb[j]);
        }
    }

    const int n0 = bn * 64 + tx * 4;
    float4 b4 = *(const float4*)&bias[n0];
#pragma unroll
    for (int i = 0; i < 8; ++i) {
        size_t m = (size_t)bm * 128 + ty * 8 + i;
        float4 o;
        o.x = upks(acc[i][0]) + b4.x;
        o.y = upks(acc[i][1]) + b4.y;
        o.z = upks(acc[i][2]) + b4.z;
        o.w = upks(acc[i][3]) + b4.w;
        *(float4*)&C[m * G3 + n0] = o;
    }
}

// ---------------------------------------------------------------------------
// Recurrent scan. Grid = 128 CTAs x 384 threads.
//   blockIdx: slice = bid & 31, group g = bid >> 5 (dir = g&1, half = g>>1)
// Each CTA: smem W slice (24 rows x 256), full h (16x256). Thread (b,row)
// computes one gh dot; threads <128 apply gate math for the CTA's 8 j's.
// ---------------------------------------------------------------------------
__global__ void __launch_bounds__(SCTH) k_scan(
    const float* __restrict__ Whh, const float* __restrict__ bhh,
    float* __restrict__ dout, int layer, int write_hn)
{
    __shared__ float sW[RPC][HPAD];
    __shared__ float sh[BC][HPAD];
    __shared__ float sgh[BC][RPC + 1];
    __shared__ float sbhh[RPC];

    const int tid = threadIdx.x;
    const int slice = blockIdx.x & 31;
    const int g = blockIdx.x >> 5;
    const int dir = g & 1;
    const int b0 = (g >> 1) * BC;

    const float* gx = &g_gx[0];
    float* out = layer ? dout : &g_out0[0];
    float* hn = (write_hn && layer >= 0) ? dout + (size_t)NBATCH * S_LEN * OUTW
                                         : nullptr;
    if (!write_hn) hn = nullptr;

    // load W slice + b_hh slice
    for (int i = tid; i < RPC * 64; i += SCTH) {
        int r = i >> 6, k4 = i & 63;
        int grow = (r >> 3) * HID + slice * 8 + (r & 7);
        *(float4*)&sW[r][k4 * 4] =
            *(const float4*)&Whh[(size_t)grow * HID + k4 * 4];
    }
    if (tid < RPC) {
        int grow = (tid >> 3) * HID + slice * 8 + (tid & 7);
        sbhh[tid] = bhh[grow];
    }

    const int w = tid >> 5, lane = tid & 31;
    const int bl = (w & 3) * 4 + (lane >> 3);   // batch index 0..15
    const int rr = (w >> 2) * 8 + (lane & 7);   // local row 0..23

    const int gb = tid >> 3, gj = tid & 7;      // gate phase (tid < 128)
    const int jglob = slice * 8 + gj;

    unsigned int* cnt = &g_cnt[g];
    float* hb0 = &g_hbuf[0][g][0];
    float* hb1 = &g_hbuf[1][g][0];

    __syncthreads();

    for (int t = 0; t < S_LEN; ++t) {
        const int tt = dir ? (S_LEN - 1 - t) : t;
        const float* hin = (t & 1) ? hb1 : hb0;
        float* hout = (t & 1) ? hb0 : hb1;

        // prefetch gx for gate phase (latency hidden under the dot)
        float gxr = 0.f, gxz = 0.f, gxn = 0.f, hprev = 0.f;
        if (tid < 128) {
            size_t base = ((size_t)(b0 + gb) * S_LEN + tt) * G3 + jglob;
            gxr = __ldg(gx + base);
            gxz = __ldg(gx + base + HID);
            gxn = __ldg(gx + base + 2 * HID);
        }

        // stage h into smem (L2-coherent loads: skip possibly-stale L1)
        for (int i = tid; i < BC * 64; i += SCTH) {
            int b = i >> 6, k4 = i & 63;
            float4 v = __ldcg((const float4*)&hin[b * HID + k4 * 4]);
            *(float4*)&sh[b][k4 * 4] = v;
        }
        __syncthreads();
        if (tid < 128) hprev = sh[gb][jglob];

        // dot: gh[bl][rr] = h[bl] . W[rr]
        uint64_t a01 = 0ull, a23 = 0ull;
        {
            const ulonglong2* hp = (const ulonglong2*)&sh[bl][0];
            const ulonglong2* wp = (const ulonglong2*)&sW[rr][0];
#pragma unroll 8
            for (int k4 = 0; k4 < 64; ++k4) {
                ulonglong2 hv = hp[k4];
                ulonglong2 wv = wp[k4];
                fma2(a01, hv.x, wv.x);
                fma2(a23, hv.y, wv.y);
            }
        }
        sgh[bl][rr] = upks(a01) + upks(a23) + sbhh[rr];
        __syncthreads();

        if (tid < 128) {
            float hr = sgh[gb][gj];
            float hz = sgh[gb][8 + gj];
            float hv = sgh[gb][16 + gj];
            float rg = 1.f / (1.f + __expf(-(gxr + hr)));
            float zg = 1.f / (1.f + __expf(-(gxz + hz)));
            float ng = tanhf(gxn + rg * hv);
            float hnew = (1.f - zg) * ng + zg * hprev;
            __stcg(&hout[gb * HID + jglob], hnew);
            out[((size_t)(b0 + gb) * S_LEN + tt) * OUTW + dir * HID + jglob] = hnew;
            if (hn && t == S_LEN - 1)
                hn[((size_t)(layer * 2 + dir) * NBATCH + b0 + gb) * HID + jglob] = hnew;
            __threadfence();
        }
        __syncthreads();

        if (t < S_LEN - 1) {
            if (tid == 0) {
                asm volatile("red.release.gpu.global.add.u32 [%0], 1;"
                             :: "l"(cnt) : "memory");
                unsigned int target = (unsigned)(t + 1) * NSLICE;
                unsigned int v;
                do {
                    asm volatile("ld.acquire.gpu.global.u32 %0, [%1];"
                                 : "=r"(v) : "l"(cnt) : "memory");
                } while (v < target);
            }
            __syncthreads();
        }
    }
}

// ---------------------------------------------------------------------------
extern "C" void kernel_launch(void* const* d_in, const int* in_sizes, int n_in,
                              void* d_out, int out_size)
{
    const float* X     = (const float*)d_in[0];
    const float* Wih0  = (const float*)d_in[1];
    const float* Whh0  = (const float*)d_in[2];
    const float* bih0  = (const float*)d_in[3];
    const float* bhh0  = (const float*)d_in[4];
    const float* Wih1  = (const float*)d_in[5];
    const float* Whh1  = (const float*)d_in[6];
    const float* bih1  = (const float*)d_in[7];
    const float* bhh1  = (const float*)d_in[8];
    float* out = (float*)d_out;

    const long long need_hn =
        (long long)NBATCH * S_LEN * OUTW + 4LL * NBATCH * HID;
    int write_hn = ((long long)out_size >= need_hn) ? 1 : 0;

    dim3 ggrid(512, 12);   // 65536/128 x 768/64

    // layer 0
    k_init<<<64, 256>>>();
    k_gemm<<<ggrid, 256>>>(X, Wih0, bih0, 256, 0);
    k_scan<<<128, SCTH>>>(Whh0, bhh0, out, 0, write_hn);

    // layer 1
    k_init<<<64, 256>>>();
    k_gemm<<<ggrid, 256>>>(nullptr, Wih1, bih1, 512, 1);
    k_scan<<<128, SCTH>>>(Whh1, bhh1, out, 1, write_hn);
}

// round 4
// speedup vs baseline: 1.1347x; 1.1347x over previous
#include <cuda_runtime.h>
#include <cuda_bf16.h>
#include <cstdint>

// ---------------------------------------------------------------------------
// 2-layer bidirectional GRU. B=32, S=2048, D=256, H=256, gates=768.
//   gx = X @ W_ih^T + b_ih      (parallel GEMM)
//   per step: gh = h @ W_hh^T + b_hh
//             r=sig(xr+hr) z=sig(xz+hz) n=tanh(xn+r*hn) h'=(1-z)*n+z*h
// Scan: 128 resident CTAs = 4 groups (2 dirs x 2 batch-halves of 16) x 32
// j-slices. Each CTA: 128 threads, thread (b,j) computes ALL THREE gate dots
// for its output element (shared h load, in-register gate fusion -> no smem
// gh exchange). h exchanged per step via double-buffered global buffer +
// single release/acquire counter barrier (no per-thread membar: bar.sync
// cumulativity makes tid0's red.release carry all threads' stores).
// ---------------------------------------------------------------------------

#define S_LEN  2048
#define NBATCH 32
#define HID    256
#define G3     768
#define OUTW   512
#define NSLICE 32
#define NGROUP 4
#define BC     16
#define HPAD   260        // padded smem row stride (floats): 8 j-rows spread banks
#define SCTH   128

// device-global scratch (no allocation allowed)
__device__ float g_gx[(size_t)NBATCH * S_LEN * G3];     // [b*S+s][768]
__device__ float g_out0[(size_t)NBATCH * S_LEN * OUTW]; // layer0 output
__device__ float g_hbuf[2][NGROUP][BC * HID];           // h exchange, 2 parities
__device__ unsigned int g_cnt[NGROUP];                  // barrier counters

// ---- f32x2 helpers --------------------------------------------------------
__device__ __forceinline__ void fma2(uint64_t& d, uint64_t a, uint64_t b) {
    asm("fma.rn.f32x2 %0, %1, %2, %0;" : "+l"(d) : "l"(a), "l"(b));
}
__device__ __forceinline__ uint64_t pk(float lo, float hi) {
    uint64_t r; asm("mov.b64 %0, {%1, %2};" : "=l"(r) : "f"(lo), "f"(hi)); return r;
}
__device__ __forceinline__ float upks(uint64_t v) {
    float lo, hi; asm("mov.b64 {%0, %1}, %2;" : "=f"(lo), "=f"(hi) : "l"(v));
    return lo + hi;
}

// ---------------------------------------------------------------------------
__global__ void k_init() {
    int idx = blockIdx.x * blockDim.x + threadIdx.x;
    float* p = &g_hbuf[0][0][0];
    const int total = 2 * NGROUP * BC * HID;
    for (int i = idx; i < total; i += gridDim.x * blockDim.x) p[i] = 0.f;
    if (idx < NGROUP) g_cnt[idx] = 0u;
}

// ---------------------------------------------------------------------------
// GEMM: C[m][n] = sum_k A[m][k]*W[n][k] + bias[n]
// A: [65536][K] row-major, W: [768][K], C = g_gx [65536][768]
// Block 128(m) x 64(n), BK=8, 256 threads, per-thread 8x4, f32x2 accumulators.
// ---------------------------------------------------------------------------
__global__ void __launch_bounds__(256) k_gemm(
    const float* __restrict__ Aext, const float* __restrict__ W,
    const float* __restrict__ bias, int K, int useInternalA)
{
    __shared__ float As[8][132];
    __shared__ float Bs[8][68];

    const float* A = useInternalA ? &g_out0[0] : Aext;
    float* C = &g_gx[0];

    const int tid = threadIdx.x;
    const int bm = blockIdx.x, bn = blockIdx.y;
    const int tx = tid & 15, ty = tid >> 4;

    const int lr = tid >> 1, lq = (tid & 1) * 4;
    const float* Ap = A + (size_t)(bm * 128 + lr) * K + lq;
    const float* Bp = W + (size_t)(bn * 64 + (lr & 63)) * K + lq;
    const bool loadB = (tid < 128);

    uint64_t acc[8][4];
#pragma unroll
    for (int i = 0; i < 8; ++i)
#pragma unroll
        for (int j = 0; j < 4; ++j) acc[i][j] = 0ull;

    float4 av = *(const float4*)Ap;
    float4 bv = loadB ? *(const float4*)Bp : make_float4(0.f, 0.f, 0.f, 0.f);

    for (int kt = 0; kt < K; kt += 8) {
        __syncthreads();
        As[lq + 0][lr] = av.x; As[lq + 1][lr] = av.y;
        As[lq + 2][lr] = av.z; As[lq + 3][lr] = av.w;
        if (loadB) {
            Bs[lq + 0][lr] = bv.x; Bs[lq + 1][lr] = bv.y;
            Bs[lq + 2][lr] = bv.z; Bs[lq + 3][lr] = bv.w;
        }
        __syncthreads();
        if (kt + 8 < K) {
            av = *(const float4*)(Ap + kt + 8);
            if (loadB) bv = *(const float4*)(Bp + kt + 8);
        }
#pragma unroll
        for (int k2 = 0; k2 < 4; ++k2) {
            float4 aL0 = *(const float4*)&As[2 * k2][ty * 8];
            float4 aH0 = *(const float4*)&As[2 * k2][ty * 8 + 4];
            float4 aL1 = *(const float4*)&As[2 * k2 + 1][ty * 8];
            float4 aH1 = *(const float4*)&As[2 * k2 + 1][ty * 8 + 4];
            float4 b0  = *(const float4*)&Bs[2 * k2][tx * 4];
            float4 b1  = *(const float4*)&Bs[2 * k2 + 1][tx * 4];
            uint64_t am[8], bb[4];
            am[0] = pk(aL0.x, aL1.x); am[1] = pk(aL0.y, aL1.y);
            am[2] = pk(aL0.z, aL1.z); am[3] = pk(aL0.w, aL1.w);
            am[4] = pk(aH0.x, aH1.x); am[5] = pk(aH0.y, aH1.y);
            am[6] = pk(aH0.z, aH1.z); am[7] = pk(aH0.w, aH1.w);
            bb[0] = pk(b0.x, b1.x);   bb[1] = pk(b0.y, b1.y);
            bb[2] = pk(b0.z, b1.z);   bb[3] = pk(b0.w, b1.w);
#pragma unroll
            for (int i = 0; i < 8; ++i)
#pragma unroll
                for (int j = 0; j < 4; ++j) fma2(acc[i][j], am[i], bb[j]);
        }
    }

    const int n0 = bn * 64 + tx * 4;
    float4 b4 = *(const float4*)&bias[n0];
#pragma unroll
    for (int i = 0; i < 8; ++i) {
        size_t m = (size_t)bm * 128 + ty * 8 + i;
        float4 o;
        o.x = upks(acc[i][0]) + b4.x;
        o.y = upks(acc[i][1]) + b4.y;
        o.z = upks(acc[i][2]) + b4.z;
        o.w = upks(acc[i][3]) + b4.w;
        *(float4*)&C[m * G3 + n0] = o;
    }
}

// ---------------------------------------------------------------------------
// Recurrent scan. Grid = 128 CTAs x 128 threads.
//   blockIdx: slice = bid & 31, group g = bid >> 5 (dir = g&1, half = g>>1)
// Thread (b = tid>>3, j = tid&7) computes gh_r, gh_z, gh_n for element
// (b0+b, slice*8+j) with a single shared h load per k-quad, then applies the
// gate math in-register. No intermediate smem exchange.
// ---------------------------------------------------------------------------
__global__ void __launch_bounds__(SCTH) k_scan(
    const float* __restrict__ Whh, const float* __restrict__ bhh,
    float* __restrict__ dout, int layer, int write_hn)
{
    __shared__ float sW[3][8][HPAD];   // [gate][j][k]
    __shared__ float sh[BC][HPAD];     // staged h

    const int tid = threadIdx.x;
    const int slice = blockIdx.x & 31;
    const int g = blockIdx.x >> 5;
    const int dir = g & 1;
    const int b0 = (g >> 1) * BC;

    const int b = tid >> 3;            // 0..15
    const int j = tid & 7;             // 0..7
    const int jg = slice * 8 + j;      // global j

    const float* gx = &g_gx[0];
    float* out = layer ? dout : &g_out0[0];
    float* hn = write_hn ? dout + (size_t)NBATCH * S_LEN * OUTW : nullptr;

    // load W slice: 24 rows x 256 floats
    for (int i = tid; i < 24 * 64; i += SCTH) {
        int r = i >> 6, k4 = i & 63;
        int gi = r >> 3, jj = r & 7;
        *(float4*)&sW[gi][jj][k4 * 4] =
            *(const float4*)&Whh[(size_t)(gi * HID + slice * 8 + jj) * HID + k4 * 4];
    }
    const float bhr = __ldg(&bhh[jg]);
    const float bhz = __ldg(&bhh[HID + jg]);
    const float bhn = __ldg(&bhh[2 * HID + jg]);

    const float* gxbase = gx + (size_t)(b0 + b) * S_LEN * G3 + jg;
    float* outbase = out + ((size_t)(b0 + b) * S_LEN) * OUTW + dir * HID + jg;

    unsigned int* cnt = &g_cnt[g];
    float* hb0 = &g_hbuf[0][g][0];
    float* hb1 = &g_hbuf[1][g][0];

    __syncthreads();

    for (int t = 0; t < S_LEN; ++t) {
        const int tt = dir ? (S_LEN - 1 - t) : t;
        const float* hin = (t & 1) ? hb1 : hb0;
        float* hout = (t & 1) ? hb0 : hb1;

        // prefetch gx (hidden under staging + dot)
        const float* gp = gxbase + (size_t)tt * G3;
        float gxr = __ldg(gp);
        float gxz = __ldg(gp + HID);
        float gxn = __ldg(gp + 2 * HID);

        // stage h into smem (L2-coherent loads)
        for (int i = tid; i < BC * 64; i += SCTH) {
            int bb = i >> 6, k4 = i & 63;
            float4 v = __ldcg((const float4*)&hin[bb * HID + k4 * 4]);
            *(float4*)&sh[bb][k4 * 4] = v;
        }
        __syncthreads();
        float hprev = sh[b][jg];

        // three fused dots: gh_r / gh_z / gh_n over k=256
        uint64_t ar0 = 0ull, ar1 = 0ull, az0 = 0ull, az1 = 0ull,
                 an0 = 0ull, an1 = 0ull;
        {
            const ulonglong2* hp = (const ulonglong2*)&sh[b][0];
            const ulonglong2* wr = (const ulonglong2*)&sW[0][j][0];
            const ulonglong2* wz = (const ulonglong2*)&sW[1][j][0];
            const ulonglong2* wn = (const ulonglong2*)&sW[2][j][0];
#pragma unroll 8
            for (int k4 = 0; k4 < 64; ++k4) {
                ulonglong2 hv = hp[k4];
                ulonglong2 rv = wr[k4];
                fma2(ar0, hv.x, rv.x); fma2(ar1, hv.y, rv.y);
                ulonglong2 zv = wz[k4];
                fma2(az0, hv.x, zv.x); fma2(az1, hv.y, zv.y);
                ulonglong2 nv = wn[k4];
                fma2(an0, hv.x, nv.x); fma2(an1, hv.y, nv.y);
            }
        }
        float hr = upks(ar0) + upks(ar1) + bhr;
        float hz = upks(az0) + upks(az1) + bhz;
        float hv = upks(an0) + upks(an1) + bhn;

        float rg = 1.f / (1.f + __expf(-(gxr + hr)));
        float zg = 1.f / (1.f + __expf(-(gxz + hz)));
        float ng = tanhf(gxn + rg * hv);
        float hnew = (1.f - zg) * ng + zg * hprev;

        __stcg(&hout[b * HID + jg], hnew);
        __syncthreads();   // all hout stores issued (+ sh reads done)

        if (t < S_LEN - 1) {
            if (tid == 0) {
                // release carries the whole CTA's stores (bar.sync cumulativity)
                asm volatile("red.release.gpu.global.add.u32 [%0], 1;"
                             :: "l"(cnt) : "memory");
                unsigned int target = (unsigned)(t + 1) * NSLICE;
                unsigned int v;
                do {
                    asm volatile("ld.acquire.gpu.global.u32 %0, [%1];"
                                 : "=r"(v) : "l"(cnt) : "memory");
                } while (v < target);
            }
            // overlap the output store with tid0's spin
            outbase[(size_t)tt * OUTW] = hnew;
            __syncthreads();
        } else {
            outbase[(size_t)tt * OUTW] = hnew;
            if (hn)
                hn[((size_t)(layer * 2 + dir) * NBATCH + b0 + b) * HID + jg] = hnew;
        }
    }
}

// ---------------------------------------------------------------------------
extern "C" void kernel_launch(void* const* d_in, const int* in_sizes, int n_in,
                              void* d_out, int out_size)
{
    const float* X     = (const float*)d_in[0];
    const float* Wih0  = (const float*)d_in[1];
    const float* Whh0  = (const float*)d_in[2];
    const float* bih0  = (const float*)d_in[3];
    const float* bhh0  = (const float*)d_in[4];
    const float* Wih1  = (const float*)d_in[5];
    const float* Whh1  = (const float*)d_in[6];
    const float* bih1  = (const float*)d_in[7];
    const float* bhh1  = (const float*)d_in[8];
    float* out = (float*)d_out;

    const long long need_hn =
        (long long)NBATCH * S_LEN * OUTW + 4LL * NBATCH * HID;
    int write_hn = ((long long)out_size >= need_hn) ? 1 : 0;

    dim3 ggrid(512, 12);   // 65536/128 x 768/64

    // layer 0
    k_init<<<64, 256>>>();
    k_gemm<<<ggrid, 256>>>(X, Wih0, bih0, 256, 0);
    k_scan<<<128, SCTH>>>(Whh0, bhh0, out, 0, write_hn);

    // layer 1
    k_init<<<64, 256>>>();
    k_gemm<<<ggrid, 256>>>(nullptr, Wih1, bih1, 512, 1);
    k_scan<<<128, SCTH>>>(Whh1, bhh1, out, 1, write_hn);
}